// round 2
// baseline (speedup 1.0000x reference)
#include <cuda_runtime.h>
#include <math.h>
#include <stdint.h>

// Problem constants
#define Bb   16
#define Ss   2048
#define KN   256
#define Dd   512
#define Mtot (Bb * Ss)            // 32768
#define RSCALE 0.044194173824159216f  // 1/sqrt(512)

// ---------------------------------------------------------------------------
// Scratch (static __device__ arrays; no runtime allocation allowed)
// ---------------------------------------------------------------------------
__device__ float g_X[Mtot * Dd];          // 64 MB  embedded input
__device__ float g_Q[Mtot * Dd];          // 64 MB
__device__ float g_K[Mtot * Dd];          // 64 MB
__device__ float g_V[Mtot * Dd];          // 64 MB
__device__ float g_S[67108864];           // 256 MB scores / p values [B,S,S]
__device__ float g_invZ[Mtot];            // per-row 1/sum(exp)
__device__ float g_c[Mtot];               // softmax column sums per batch
__device__ float g_sumO[Bb * Dd];         // sum over queries of (w@v)
__device__ float g_cat[Bb * 2 * Dd];      // concat(sa0, sa1)

// ---------------------------------------------------------------------------
// Tiled GEMM: C[M,N] = A[M,Kd] @ W[Kd,N] + bias,  N = Dd = 512
// Optional per-batch row limit: skip row-tiles whose (row % S) >= len[b]+1.
// 64x64 tile, BK=16, 256 threads, 4x4 per thread.
// ---------------------------------------------------------------------------
__global__ void gemm_bias_kernel(const float* __restrict__ A,
                                 const float* __restrict__ W,
                                 const float* __restrict__ bias,
                                 float* __restrict__ C,
                                 int Kd,
                                 const int* __restrict__ lens)
{
    __shared__ float As[16][64];
    __shared__ float Bs[16][64];
    const int tid  = threadIdx.x;
    const int tx   = tid & 15;
    const int ty   = tid >> 4;
    const int row0 = blockIdx.x * 64;
    const int col0 = blockIdx.y * 64;

    if (lens) {
        const int b = row0 / Ss;
        const int L = lens[b] + 1;
        if ((row0 % Ss) >= L) return;   // uniform per block
    }

    float acc[4][4] = {};
    for (int kt = 0; kt < Kd; kt += 16) {
        #pragma unroll
        for (int it = 0; it < 4; it++) {
            const int idx = tid + it * 256;
            const int m = idx >> 4, k = idx & 15;
            As[k][m] = A[(size_t)(row0 + m) * Kd + kt + k];
        }
        #pragma unroll
        for (int it = 0; it < 4; it++) {
            const int idx = tid + it * 256;
            const int k = idx >> 6, n = idx & 63;
            Bs[k][n] = W[(size_t)(kt + k) * Dd + col0 + n];
        }
        __syncthreads();
        #pragma unroll
        for (int kk = 0; kk < 16; kk++) {
            float a[4], bv[4];
            #pragma unroll
            for (int i = 0; i < 4; i++) a[i]  = As[kk][ty * 4 + i];
            #pragma unroll
            for (int j = 0; j < 4; j++) bv[j] = Bs[kk][tx * 4 + j];
            #pragma unroll
            for (int i = 0; i < 4; i++)
                #pragma unroll
                for (int j = 0; j < 4; j++)
                    acc[i][j] += a[i] * bv[j];
        }
        __syncthreads();
    }
    #pragma unroll
    for (int i = 0; i < 4; i++) {
        const int r = row0 + ty * 4 + i;
        #pragma unroll
        for (int j = 0; j < 4; j++) {
            const int cidx = col0 + tx * 4 + j;
            C[(size_t)r * Dd + cidx] = acc[i][j] + bias[cidx];
        }
    }
}

// ---------------------------------------------------------------------------
// Embed GEMM: X[m,:] = (emb_table[data[m]] * know[m,:]) @ W_t + b_t
// A built on the fly from gather * elementwise. Kd = KN = 256.
// ---------------------------------------------------------------------------
__global__ void embed_gemm_kernel(const int* __restrict__ data,
                                  const float* __restrict__ know,
                                  const float* __restrict__ emb,
                                  const float* __restrict__ Wt,
                                  const float* __restrict__ bt,
                                  float* __restrict__ C)
{
    __shared__ float As[16][64];
    __shared__ float Bs[16][64];
    __shared__ int   sIdx[64];
    const int tid  = threadIdx.x;
    const int tx   = tid & 15;
    const int ty   = tid >> 4;
    const int row0 = blockIdx.x * 64;
    const int col0 = blockIdx.y * 64;

    if (tid < 64) sIdx[tid] = data[row0 + tid];
    __syncthreads();

    float acc[4][4] = {};
    for (int kt = 0; kt < KN; kt += 16) {
        #pragma unroll
        for (int it = 0; it < 4; it++) {
            const int idx = tid + it * 256;
            const int m = idx >> 4, k = idx & 15;
            const float e  = emb[(size_t)sIdx[m] * KN + kt + k];
            const float kn = know[(size_t)(row0 + m) * KN + kt + k];
            As[k][m] = e * kn;
        }
        #pragma unroll
        for (int it = 0; it < 4; it++) {
            const int idx = tid + it * 256;
            const int k = idx >> 6, n = idx & 63;
            Bs[k][n] = Wt[(size_t)(kt + k) * Dd + col0 + n];
        }
        __syncthreads();
        #pragma unroll
        for (int kk = 0; kk < 16; kk++) {
            float a[4], bv[4];
            #pragma unroll
            for (int i = 0; i < 4; i++) a[i]  = As[kk][ty * 4 + i];
            #pragma unroll
            for (int j = 0; j < 4; j++) bv[j] = Bs[kk][tx * 4 + j];
            #pragma unroll
            for (int i = 0; i < 4; i++)
                #pragma unroll
                for (int j = 0; j < 4; j++)
                    acc[i][j] += a[i] * bv[j];
        }
        __syncthreads();
    }
    #pragma unroll
    for (int i = 0; i < 4; i++) {
        const int r = row0 + ty * 4 + i;
        #pragma unroll
        for (int j = 0; j < 4; j++) {
            const int cidx = col0 + tx * 4 + j;
            C[(size_t)r * Dd + cidx] = acc[i][j] + bt[cidx];
        }
    }
}

// ---------------------------------------------------------------------------
// Scores: S[b,q,k] = RSCALE * dot(Q[b,q,:], K[b,k,:])  (NT GEMM per batch)
// Skips k-tiles entirely beyond the key mask (consumers never read k >= L).
// ---------------------------------------------------------------------------
__global__ void scores_kernel(const float* __restrict__ Q,
                              const float* __restrict__ Km,
                              float* __restrict__ Sout,
                              const int* __restrict__ lens)
{
    const int b  = blockIdx.z;
    const int q0 = blockIdx.x * 64;
    const int k0 = blockIdx.y * 64;
    const int L  = lens[b] + 1;
    if (k0 >= L) return;

    __shared__ float As[16][64];
    __shared__ float Bs[16][64];
    const int tid = threadIdx.x;
    const int tx  = tid & 15;
    const int ty  = tid >> 4;

    const float* Qb = Q  + (size_t)b * Ss * Dd;
    const float* Kb = Km + (size_t)b * Ss * Dd;

    float acc[4][4] = {};
    for (int kt = 0; kt < Dd; kt += 16) {
        #pragma unroll
        for (int it = 0; it < 4; it++) {
            const int idx = tid + it * 256;
            const int m = idx >> 4, k = idx & 15;
            As[k][m] = Qb[(size_t)(q0 + m) * Dd + kt + k];
        }
        #pragma unroll
        for (int it = 0; it < 4; it++) {
            const int idx = tid + it * 256;
            const int n = idx >> 4, k = idx & 15;
            Bs[k][n] = Kb[(size_t)(k0 + n) * Dd + kt + k];
        }
        __syncthreads();
        #pragma unroll
        for (int kk = 0; kk < 16; kk++) {
            float a[4], bv[4];
            #pragma unroll
            for (int i = 0; i < 4; i++) a[i]  = As[kk][ty * 4 + i];
            #pragma unroll
            for (int j = 0; j < 4; j++) bv[j] = Bs[kk][tx * 4 + j];
            #pragma unroll
            for (int i = 0; i < 4; i++)
                #pragma unroll
                for (int j = 0; j < 4; j++)
                    acc[i][j] += a[i] * bv[j];
        }
        __syncthreads();
    }
    float* Sb = Sout + (size_t)b * Ss * Ss;
    #pragma unroll
    for (int i = 0; i < 4; i++) {
        const int q = q0 + ty * 4 + i;
        #pragma unroll
        for (int j = 0; j < 4; j++)
            Sb[(size_t)q * Ss + k0 + tx * 4 + j] = acc[i][j] * RSCALE;
    }
}

// ---------------------------------------------------------------------------
// Row stats: per (b,q) row of scores: m = max, then overwrite s with
// p = exp(s - m) in place, store invZ = 1/sum(p). Block = one row, 256 thr.
// ---------------------------------------------------------------------------
__global__ void rowstats_kernel(float* __restrict__ Sm,
                                float* __restrict__ invZ,
                                const int* __restrict__ lens)
{
    __shared__ float red[256];
    const int r   = blockIdx.x;            // r = b*S + q
    const int b   = r / Ss;
    const int L   = lens[b] + 1;
    const int tid = threadIdx.x;
    float* row = Sm + (size_t)r * Ss;

    float mx = -1e30f;
    for (int k = tid; k < L; k += 256) mx = fmaxf(mx, row[k]);
    red[tid] = mx;
    __syncthreads();
    for (int s = 128; s > 0; s >>= 1) {
        if (tid < s) red[tid] = fmaxf(red[tid], red[tid + s]);
        __syncthreads();
    }
    mx = red[0];
    __syncthreads();

    float z = 0.f;
    for (int k = tid; k < L; k += 256) {
        const float p = expf(row[k] - mx);
        row[k] = p;
        z += p;
    }
    red[tid] = z;
    __syncthreads();
    for (int s = 128; s > 0; s >>= 1) {
        if (tid < s) red[tid] += red[tid + s];
        __syncthreads();
    }
    if (tid == 0) invZ[r] = 1.0f / red[0];
}

// ---------------------------------------------------------------------------
// Column sums: c[b,k] = sum_q p[b,q,k] * invZ[b,q];  c = 0 for masked keys.
// Coalesced column walk, no atomics.
// ---------------------------------------------------------------------------
__global__ void colsum_kernel(const float* __restrict__ Sm,
                              const float* __restrict__ invZ,
                              float* __restrict__ c,
                              const int* __restrict__ lens)
{
    const int b = blockIdx.y;
    const int k = blockIdx.x * 256 + threadIdx.x;
    const int L = lens[b] + 1;
    if (k >= L) { c[b * Ss + k] = 0.0f; return; }

    const float* sp = Sm + (size_t)b * Ss * Ss + k;
    const float* iz = invZ + b * Ss;
    float acc = 0.f;
    #pragma unroll 1
    for (int q = 0; q < Ss; q += 8) {
        float p0 = sp[(size_t)(q + 0) * Ss];
        float p1 = sp[(size_t)(q + 1) * Ss];
        float p2 = sp[(size_t)(q + 2) * Ss];
        float p3 = sp[(size_t)(q + 3) * Ss];
        float p4 = sp[(size_t)(q + 4) * Ss];
        float p5 = sp[(size_t)(q + 5) * Ss];
        float p6 = sp[(size_t)(q + 6) * Ss];
        float p7 = sp[(size_t)(q + 7) * Ss];
        acc += p0 * iz[q + 0] + p1 * iz[q + 1] + p2 * iz[q + 2] + p3 * iz[q + 3]
             + p4 * iz[q + 4] + p5 * iz[q + 5] + p6 * iz[q + 6] + p7 * iz[q + 7];
    }
    c[b * Ss + k] = acc;
}

// ---------------------------------------------------------------------------
// sumO[b,d] = sum_{k<L} c[b,k] * V[b,k,d]
// ---------------------------------------------------------------------------
__global__ void sumo_kernel(const float* __restrict__ c,
                            const float* __restrict__ V,
                            float* __restrict__ sumO,
                            const int* __restrict__ lens)
{
    const int b = blockIdx.y;
    const int d = blockIdx.x * 128 + threadIdx.x;
    const int L = lens[b] + 1;
    const float* Vb = V + (size_t)b * Ss * Dd;
    const float* cb = c + b * Ss;
    float acc = 0.f;
    #pragma unroll 4
    for (int k = 0; k < L; k++)
        acc += cb[k] * Vb[(size_t)k * Dd + d];
    sumO[b * Dd + d] = acc;
}

// ---------------------------------------------------------------------------
// sa[b,n] = sumO[b,:] @ Wo[:,n] + S * bo[n]   -> g_cat[b, st*D + n]
// ---------------------------------------------------------------------------
__global__ void sa_kernel(const float* __restrict__ sumO,
                          const float* __restrict__ Wo,
                          const float* __restrict__ bo,
                          float* __restrict__ cat,
                          int st)
{
    __shared__ float sO[Dd];
    const int b = blockIdx.y;
    const int n = blockIdx.x * 256 + threadIdx.x;
    for (int i = threadIdx.x; i < Dd; i += 256) sO[i] = sumO[b * Dd + i];
    __syncthreads();
    float acc = (float)Ss * bo[n];
    #pragma unroll 8
    for (int d = 0; d < Dd; d++)
        acc += sO[d] * Wo[(size_t)d * Dd + n];
    cat[b * (2 * Dd) + st * Dd + n] = acc;
}

// ---------------------------------------------------------------------------
// out[b,j] = tanh(cat[b,:] @ W_out[:,j] + b_out[j])
// ---------------------------------------------------------------------------
__global__ void final_kernel(const float* __restrict__ cat,
                             const float* __restrict__ Wout,
                             const float* __restrict__ bout,
                             float* __restrict__ out)
{
    __shared__ float sc[2 * Dd];
    const int b = blockIdx.x;
    const int j = threadIdx.x;      // 256 threads = KN outputs
    for (int i = threadIdx.x; i < 2 * Dd; i += 256) sc[i] = cat[b * (2 * Dd) + i];
    __syncthreads();
    float acc = bout[j];
    #pragma unroll 8
    for (int i = 0; i < 2 * Dd; i++)
        acc += sc[i] * Wout[(size_t)i * KN + j];
    out[b * KN + j] = tanhf(acc);
}

// ---------------------------------------------------------------------------
// Launch
// ---------------------------------------------------------------------------
extern "C" void kernel_launch(void* const* d_in, const int* in_sizes, int n_in,
                              void* d_out, int out_size)
{
    // Inputs in metadata order
    const int*   data0 = (const int*)  d_in[0];
    const float* know0 = (const float*)d_in[1];
    const int*   len0  = (const int*)  d_in[2];
    const int*   data1 = (const int*)  d_in[3];
    const float* know1 = (const float*)d_in[4];
    const int*   len1  = (const int*)  d_in[5];
    const float* emb   = (const float*)d_in[6];
    const float* Wt    = (const float*)d_in[7];
    const float* bt    = (const float*)d_in[8];
    // per-stream attention weights: Wq,bq,Wk,bk,Wv,bv,Wo,bo (stream0 then stream1)
    const float* Wq[2] = {(const float*)d_in[9],  (const float*)d_in[17]};
    const float* bq[2] = {(const float*)d_in[10], (const float*)d_in[18]};
    const float* Wk[2] = {(const float*)d_in[11], (const float*)d_in[19]};
    const float* bk[2] = {(const float*)d_in[12], (const float*)d_in[20]};
    const float* Wv[2] = {(const float*)d_in[13], (const float*)d_in[21]};
    const float* bv[2] = {(const float*)d_in[14], (const float*)d_in[22]};
    const float* Wo[2] = {(const float*)d_in[15], (const float*)d_in[23]};
    const float* bo[2] = {(const float*)d_in[16], (const float*)d_in[24]};
    const float* Wout  = (const float*)d_in[25];
    const float* bout  = (const float*)d_in[26];
    float* out = (float*)d_out;

    const int*   datas[2] = {data0, data1};
    const float* knows[2] = {know0, know1};
    const int*   lens [2] = {len0, len1};

    // resolve device symbol addresses (host-side, not captured)
    float *pX, *pQ, *pK, *pV, *pS, *pIZ, *pC, *pSO, *pCat;
    cudaGetSymbolAddress((void**)&pX,  g_X);
    cudaGetSymbolAddress((void**)&pQ,  g_Q);
    cudaGetSymbolAddress((void**)&pK,  g_K);
    cudaGetSymbolAddress((void**)&pV,  g_V);
    cudaGetSymbolAddress((void**)&pS,  g_S);
    cudaGetSymbolAddress((void**)&pIZ, g_invZ);
    cudaGetSymbolAddress((void**)&pC,  g_c);
    cudaGetSymbolAddress((void**)&pSO, g_sumO);
    cudaGetSymbolAddress((void**)&pCat,g_cat);

    const dim3 gGemm(Mtot / 64, Dd / 64);    // 512 x 8
    const dim3 gScore(Ss / 64, Ss / 64, Bb); // 32 x 32 x 16

    for (int st = 0; st < 2; st++) {
        // 1) embed:  X = (emb[data]*know) @ Wt + bt
        embed_gemm_kernel<<<gGemm, 256>>>(datas[st], knows[st], emb, Wt, bt, pX);
        // 2) Q (all rows), K,V (masked row-tiles skipped)
        gemm_bias_kernel<<<gGemm, 256>>>(pX, Wq[st], bq[st], pQ, Dd, nullptr);
        gemm_bias_kernel<<<gGemm, 256>>>(pX, Wk[st], bk[st], pK, Dd, lens[st]);
        gemm_bias_kernel<<<gGemm, 256>>>(pX, Wv[st], bv[st], pV, Dd, lens[st]);
        // 3) scores (masked k-tiles skipped)
        scores_kernel<<<gScore, 256>>>(pQ, pK, pS, lens[st]);
        // 4) softmax row stats (writes p in place) + column sums
        rowstats_kernel<<<Mtot, 256>>>(pS, pIZ, lens[st]);
        colsum_kernel<<<dim3(Ss / 256, Bb), 256>>>(pS, pIZ, pC, lens[st]);
        // 5) sumO = c @ V ; sa = sumO @ Wo + S*bo -> cat slot
        sumo_kernel<<<dim3(Dd / 128, Bb), 128>>>(pC, pV, pSO, lens[st]);
        sa_kernel<<<dim3(Dd / 256, Bb), 256>>>(pSO, Wo[st], bo[st], pCat, st);
    }
    // 6) out = tanh(cat @ Wout + bout)
    final_kernel<<<Bb, 256>>>(pCat, Wout, bout, out);
}

// round 5
// speedup vs baseline: 2.4632x; 2.4632x over previous
#include <cuda_runtime.h>
#include <math.h>
#include <stdint.h>

// Problem constants
#define Bb   16
#define Ss   2048
#define KN   256
#define Dd   512
#define Mtot (Bb * Ss)            // 32768
#define RSCALE 0.044194173824159216f  // 1/sqrt(512)

#define AS_STRIDE 136
#define BS_STRIDE 72

// ---------------------------------------------------------------------------
// Scratch (static __device__ arrays; no runtime allocation allowed)
// ---------------------------------------------------------------------------
__device__ float g_X[Mtot * Dd];          // 64 MB  embedded input
__device__ float g_Q[Mtot * Dd];          // 64 MB
__device__ float g_K[Mtot * Dd];          // 64 MB
__device__ float g_V[Mtot * Dd];          // 64 MB
__device__ float g_S[67108864];           // 256 MB scores / p values [B,S,S]
__device__ float g_invZ[Mtot];            // per-row 1/sum(exp)
__device__ float g_c[Mtot];               // softmax column sums per batch
__device__ float g_sumO[Bb * Dd];         // sum over queries of (w@v)
__device__ float g_cat[Bb * 2 * Dd];      // concat(sa0, sa1)

// ---------------------------------------------------------------------------
// tf32 helpers
// ---------------------------------------------------------------------------
__device__ __forceinline__ uint32_t f2tf(float f) {
    uint32_t r;
    asm("cvt.rna.tf32.f32 %0, %1;" : "=r"(r) : "f"(f));
    return r;
}

__device__ __forceinline__ void mma8(float c[4], const uint32_t a[4], const uint32_t b[2]) {
    asm volatile(
        "mma.sync.aligned.m16n8k8.row.col.f32.tf32.tf32.f32 "
        "{%0,%1,%2,%3}, {%4,%5,%6,%7}, {%8,%9}, {%0,%1,%2,%3};"
        : "+f"(c[0]), "+f"(c[1]), "+f"(c[2]), "+f"(c[3])
        : "r"(a[0]), "r"(a[1]), "r"(a[2]), "r"(a[3]), "r"(b[0]), "r"(b[1]));
}

// Warp-level compute for one BK=16 slab. Warp (wm,wn) owns a 32x32 subtile.
__device__ __forceinline__ void compute_bk(const uint32_t As[16][AS_STRIDE],
                                           const uint32_t Bs[16][BS_STRIDE],
                                           float acc[2][4][4],
                                           int lane, int wm, int wn)
{
    const int grp = lane >> 2;   // 0..7
    const int qd  = lane & 3;    // 0..3
    #pragma unroll
    for (int ks = 0; ks < 2; ks++) {
        const int k0 = ks * 8;
        uint32_t a[2][4], b[4][2];
        #pragma unroll
        for (int tm = 0; tm < 2; tm++) {
            const int m = wm * 32 + tm * 16 + grp;
            a[tm][0] = As[k0 + qd][m];
            a[tm][1] = As[k0 + qd][m + 8];
            a[tm][2] = As[k0 + qd + 4][m];
            a[tm][3] = As[k0 + qd + 4][m + 8];
        }
        #pragma unroll
        for (int tn = 0; tn < 4; tn++) {
            const int n = wn * 32 + tn * 8 + grp;
            b[tn][0] = Bs[k0 + qd][n];
            b[tn][1] = Bs[k0 + qd + 4][n];
        }
        #pragma unroll
        for (int tm = 0; tm < 2; tm++)
            #pragma unroll
            for (int tn = 0; tn < 4; tn++)
                mma8(acc[tm][tn], a[tm], b[tn]);
    }
}

// ---------------------------------------------------------------------------
// tf32 GEMM: C[M,512] = A[M,Kd] @ W[Kd,512] + bias. Optional masked row-tiles.
// CTA 128x64, BK=16, 256 threads.
// ---------------------------------------------------------------------------
__global__ __launch_bounds__(256) void tf32_gemm_bias(const float* __restrict__ A,
                                                      const float* __restrict__ W,
                                                      const float* __restrict__ bias,
                                                      float* __restrict__ C,
                                                      int Kd,
                                                      const int* __restrict__ lens)
{
    __shared__ uint32_t As[16][AS_STRIDE];
    __shared__ uint32_t Bs[16][BS_STRIDE];
    const int tid  = threadIdx.x;
    const int lane = tid & 31;
    const int w    = tid >> 5;
    const int wm   = w & 3, wn = w >> 2;
    const int row0 = blockIdx.x * 128;
    const int col0 = blockIdx.y * 64;

    if (lens) {
        const int L = lens[row0 / Ss] + 1;
        if ((row0 % Ss) >= L) return;
    }

    const int ar  = tid >> 2;        // 0..63 (second copy +64)
    const int akq = (tid & 3) * 4;   // k quad offset
    const int bk  = tid >> 4;        // 0..15
    const int bn  = (tid & 15) * 4;

    float4 ra0 = *(const float4*)&A[(size_t)(row0 + ar) * Kd + akq];
    float4 ra1 = *(const float4*)&A[(size_t)(row0 + ar + 64) * Kd + akq];
    float4 rb  = *(const float4*)&W[(size_t)bk * Dd + col0 + bn];

    float acc[2][4][4] = {};
    for (int kt = 0; kt < Kd; kt += 16) {
        As[akq + 0][ar] = f2tf(ra0.x); As[akq + 1][ar] = f2tf(ra0.y);
        As[akq + 2][ar] = f2tf(ra0.z); As[akq + 3][ar] = f2tf(ra0.w);
        As[akq + 0][ar + 64] = f2tf(ra1.x); As[akq + 1][ar + 64] = f2tf(ra1.y);
        As[akq + 2][ar + 64] = f2tf(ra1.z); As[akq + 3][ar + 64] = f2tf(ra1.w);
        Bs[bk][bn + 0] = f2tf(rb.x); Bs[bk][bn + 1] = f2tf(rb.y);
        Bs[bk][bn + 2] = f2tf(rb.z); Bs[bk][bn + 3] = f2tf(rb.w);
        __syncthreads();
        if (kt + 16 < Kd) {
            ra0 = *(const float4*)&A[(size_t)(row0 + ar) * Kd + kt + 16 + akq];
            ra1 = *(const float4*)&A[(size_t)(row0 + ar + 64) * Kd + kt + 16 + akq];
            rb  = *(const float4*)&W[(size_t)(kt + 16 + bk) * Dd + col0 + bn];
        }
        compute_bk(As, Bs, acc, lane, wm, wn);
        __syncthreads();
    }

    const int grp = lane >> 2, qd = lane & 3;
    #pragma unroll
    for (int tm = 0; tm < 2; tm++) {
        #pragma unroll
        for (int tn = 0; tn < 4; tn++) {
            const int r = row0 + wm * 32 + tm * 16 + grp;
            const int c = col0 + wn * 32 + tn * 8 + qd * 2;
            const float b0 = bias[c], b1 = bias[c + 1];
            C[(size_t)r * Dd + c]           = acc[tm][tn][0] + b0;
            C[(size_t)r * Dd + c + 1]       = acc[tm][tn][1] + b1;
            C[(size_t)(r + 8) * Dd + c]     = acc[tm][tn][2] + b0;
            C[(size_t)(r + 8) * Dd + c + 1] = acc[tm][tn][3] + b1;
        }
    }
}

// ---------------------------------------------------------------------------
// Embed GEMM (tf32): X = (emb[data]*know) @ W_t + b_t,  Kd = 256
// ---------------------------------------------------------------------------
__global__ __launch_bounds__(256) void tf32_embed_gemm(const int* __restrict__ data,
                                                       const float* __restrict__ know,
                                                       const float* __restrict__ emb,
                                                       const float* __restrict__ Wt,
                                                       const float* __restrict__ bt,
                                                       float* __restrict__ C)
{
    __shared__ uint32_t As[16][AS_STRIDE];
    __shared__ uint32_t Bs[16][BS_STRIDE];
    __shared__ int sIdx[128];
    const int tid  = threadIdx.x;
    const int lane = tid & 31;
    const int w    = tid >> 5;
    const int wm   = w & 3, wn = w >> 2;
    const int row0 = blockIdx.x * 128;
    const int col0 = blockIdx.y * 64;

    if (tid < 128) sIdx[tid] = data[row0 + tid];
    __syncthreads();

    const int ar  = tid >> 2;
    const int akq = (tid & 3) * 4;
    const int bk  = tid >> 4;
    const int bn  = (tid & 15) * 4;

    const size_t e0 = (size_t)sIdx[ar] * KN;
    const size_t e1 = (size_t)sIdx[ar + 64] * KN;
    const size_t k0r = (size_t)(row0 + ar) * KN;
    const size_t k1r = (size_t)(row0 + ar + 64) * KN;

    float4 ea0 = *(const float4*)&emb[e0 + akq];
    float4 ka0 = *(const float4*)&know[k0r + akq];
    float4 ea1 = *(const float4*)&emb[e1 + akq];
    float4 ka1 = *(const float4*)&know[k1r + akq];
    float4 rb  = *(const float4*)&Wt[(size_t)bk * Dd + col0 + bn];

    float acc[2][4][4] = {};
    for (int kt = 0; kt < KN; kt += 16) {
        As[akq + 0][ar] = f2tf(ea0.x * ka0.x); As[akq + 1][ar] = f2tf(ea0.y * ka0.y);
        As[akq + 2][ar] = f2tf(ea0.z * ka0.z); As[akq + 3][ar] = f2tf(ea0.w * ka0.w);
        As[akq + 0][ar + 64] = f2tf(ea1.x * ka1.x); As[akq + 1][ar + 64] = f2tf(ea1.y * ka1.y);
        As[akq + 2][ar + 64] = f2tf(ea1.z * ka1.z); As[akq + 3][ar + 64] = f2tf(ea1.w * ka1.w);
        Bs[bk][bn + 0] = f2tf(rb.x); Bs[bk][bn + 1] = f2tf(rb.y);
        Bs[bk][bn + 2] = f2tf(rb.z); Bs[bk][bn + 3] = f2tf(rb.w);
        __syncthreads();
        if (kt + 16 < KN) {
            ea0 = *(const float4*)&emb[e0 + kt + 16 + akq];
            ka0 = *(const float4*)&know[k0r + kt + 16 + akq];
            ea1 = *(const float4*)&emb[e1 + kt + 16 + akq];
            ka1 = *(const float4*)&know[k1r + kt + 16 + akq];
            rb  = *(const float4*)&Wt[(size_t)(kt + 16 + bk) * Dd + col0 + bn];
        }
        compute_bk(As, Bs, acc, lane, wm, wn);
        __syncthreads();
    }

    const int grp = lane >> 2, qd = lane & 3;
    #pragma unroll
    for (int tm = 0; tm < 2; tm++) {
        #pragma unroll
        for (int tn = 0; tn < 4; tn++) {
            const int r = row0 + wm * 32 + tm * 16 + grp;
            const int c = col0 + wn * 32 + tn * 8 + qd * 2;
            const float b0 = bt[c], b1 = bt[c + 1];
            C[(size_t)r * Dd + c]           = acc[tm][tn][0] + b0;
            C[(size_t)r * Dd + c + 1]       = acc[tm][tn][1] + b1;
            C[(size_t)(r + 8) * Dd + c]     = acc[tm][tn][2] + b0;
            C[(size_t)(r + 8) * Dd + c + 1] = acc[tm][tn][3] + b1;
        }
    }
}

// ---------------------------------------------------------------------------
// Scores (tf32, NT): S[b,q,k] = RSCALE * dot(Q[b,q,:], K[b,k,:]). Masked
// k-tiles skipped. CTA 128(q) x 64(k), BK=16 over D=512.
// ---------------------------------------------------------------------------
__global__ __launch_bounds__(256) void tf32_scores(const float* __restrict__ Q,
                                                   const float* __restrict__ Km,
                                                   float* __restrict__ Sout,
                                                   const int* __restrict__ lens)
{
    const int b  = blockIdx.z;
    const int q0 = blockIdx.x * 128;
    const int k0c = blockIdx.y * 64;
    const int L  = lens[b] + 1;
    if (k0c >= L) return;

    __shared__ uint32_t As[16][AS_STRIDE];
    __shared__ uint32_t Bs[16][BS_STRIDE];
    const int tid  = threadIdx.x;
    const int lane = tid & 31;
    const int w    = tid >> 5;
    const int wm   = w & 3, wn = w >> 2;

    const float* Qb = Q  + (size_t)b * Ss * Dd;
    const float* Kb = Km + (size_t)b * Ss * Dd;

    const int ar  = tid >> 2;
    const int akq = (tid & 3) * 4;
    const int bnr = tid >> 2;         // K row within tile (0..63)
    const int bkq = (tid & 3) * 4;

    float4 ra0 = *(const float4*)&Qb[(size_t)(q0 + ar) * Dd + akq];
    float4 ra1 = *(const float4*)&Qb[(size_t)(q0 + ar + 64) * Dd + akq];
    float4 rb  = *(const float4*)&Kb[(size_t)(k0c + bnr) * Dd + bkq];

    float acc[2][4][4] = {};
    for (int kt = 0; kt < Dd; kt += 16) {
        As[akq + 0][ar] = f2tf(ra0.x); As[akq + 1][ar] = f2tf(ra0.y);
        As[akq + 2][ar] = f2tf(ra0.z); As[akq + 3][ar] = f2tf(ra0.w);
        As[akq + 0][ar + 64] = f2tf(ra1.x); As[akq + 1][ar + 64] = f2tf(ra1.y);
        As[akq + 2][ar + 64] = f2tf(ra1.z); As[akq + 3][ar + 64] = f2tf(ra1.w);
        Bs[bkq + 0][bnr] = f2tf(rb.x); Bs[bkq + 1][bnr] = f2tf(rb.y);
        Bs[bkq + 2][bnr] = f2tf(rb.z); Bs[bkq + 3][bnr] = f2tf(rb.w);
        __syncthreads();
        if (kt + 16 < Dd) {
            ra0 = *(const float4*)&Qb[(size_t)(q0 + ar) * Dd + kt + 16 + akq];
            ra1 = *(const float4*)&Qb[(size_t)(q0 + ar + 64) * Dd + kt + 16 + akq];
            rb  = *(const float4*)&Kb[(size_t)(k0c + bnr) * Dd + kt + 16 + bkq];
        }
        compute_bk(As, Bs, acc, lane, wm, wn);
        __syncthreads();
    }

    float* Sb = Sout + (size_t)b * Ss * Ss;
    const int grp = lane >> 2, qd = lane & 3;
    #pragma unroll
    for (int tm = 0; tm < 2; tm++) {
        #pragma unroll
        for (int tn = 0; tn < 4; tn++) {
            const int q = q0 + wm * 32 + tm * 16 + grp;
            const int k = k0c + wn * 32 + tn * 8 + qd * 2;
            Sb[(size_t)q * Ss + k]           = acc[tm][tn][0] * RSCALE;
            Sb[(size_t)q * Ss + k + 1]       = acc[tm][tn][1] * RSCALE;
            Sb[(size_t)(q + 8) * Ss + k]     = acc[tm][tn][2] * RSCALE;
            Sb[(size_t)(q + 8) * Ss + k + 1] = acc[tm][tn][3] * RSCALE;
        }
    }
}

// ---------------------------------------------------------------------------
// Row stats: per (b,q) row: m = max, p = exp(s - m) in place, invZ = 1/sum(p)
// ---------------------------------------------------------------------------
__global__ void rowstats_kernel(float* __restrict__ Sm,
                                float* __restrict__ invZ,
                                const int* __restrict__ lens)
{
    __shared__ float red[256];
    const int r   = blockIdx.x;            // r = b*S + q
    const int b   = r / Ss;
    const int L   = lens[b] + 1;
    const int tid = threadIdx.x;
    float* row = Sm + (size_t)r * Ss;

    float mx = -1e30f;
    for (int k = tid; k < L; k += 256) mx = fmaxf(mx, row[k]);
    red[tid] = mx;
    __syncthreads();
    for (int s = 128; s > 0; s >>= 1) {
        if (tid < s) red[tid] = fmaxf(red[tid], red[tid + s]);
        __syncthreads();
    }
    mx = red[0];
    __syncthreads();

    float z = 0.f;
    for (int k = tid; k < L; k += 256) {
        const float p = expf(row[k] - mx);
        row[k] = p;
        z += p;
    }
    red[tid] = z;
    __syncthreads();
    for (int s = 128; s > 0; s >>= 1) {
        if (tid < s) red[tid] += red[tid + s];
        __syncthreads();
    }
    if (tid == 0) invZ[r] = 1.0f / red[0];
}

// ---------------------------------------------------------------------------
// Column sums: c[b,k] = sum_q p[b,q,k] * invZ[b,q]
// ---------------------------------------------------------------------------
__global__ void colsum_kernel(const float* __restrict__ Sm,
                              const float* __restrict__ invZ,
                              float* __restrict__ c,
                              const int* __restrict__ lens)
{
    const int b = blockIdx.y;
    const int k = blockIdx.x * 256 + threadIdx.x;
    const int L = lens[b] + 1;
    if (k >= L) { c[b * Ss + k] = 0.0f; return; }

    const float* sp = Sm + (size_t)b * Ss * Ss + k;
    const float* iz = invZ + b * Ss;
    float acc = 0.f;
    #pragma unroll 1
    for (int q = 0; q < Ss; q += 8) {
        float p0 = sp[(size_t)(q + 0) * Ss];
        float p1 = sp[(size_t)(q + 1) * Ss];
        float p2 = sp[(size_t)(q + 2) * Ss];
        float p3 = sp[(size_t)(q + 3) * Ss];
        float p4 = sp[(size_t)(q + 4) * Ss];
        float p5 = sp[(size_t)(q + 5) * Ss];
        float p6 = sp[(size_t)(q + 6) * Ss];
        float p7 = sp[(size_t)(q + 7) * Ss];
        acc += p0 * iz[q + 0] + p1 * iz[q + 1] + p2 * iz[q + 2] + p3 * iz[q + 3]
             + p4 * iz[q + 4] + p5 * iz[q + 5] + p6 * iz[q + 6] + p7 * iz[q + 7];
    }
    c[b * Ss + k] = acc;
}

// ---------------------------------------------------------------------------
// sumO[b,d] = sum_{k<L} c[b,k] * V[b,k,d]
// ---------------------------------------------------------------------------
__global__ void sumo_kernel(const float* __restrict__ c,
                            const float* __restrict__ V,
                            float* __restrict__ sumO,
                            const int* __restrict__ lens)
{
    const int b = blockIdx.y;
    const int d = blockIdx.x * 128 + threadIdx.x;
    const int L = lens[b] + 1;
    const float* Vb = V + (size_t)b * Ss * Dd;
    const float* cb = c + b * Ss;
    float acc = 0.f;
    #pragma unroll 4
    for (int k = 0; k < L; k++)
        acc += cb[k] * Vb[(size_t)k * Dd + d];
    sumO[b * Dd + d] = acc;
}

// ---------------------------------------------------------------------------
// sa[b,n] = sumO[b,:] @ Wo[:,n] + S * bo[n]   -> g_cat[b, st*D + n]
// ---------------------------------------------------------------------------
__global__ void sa_kernel(const float* __restrict__ sumO,
                          const float* __restrict__ Wo,
                          const float* __restrict__ bo,
                          float* __restrict__ cat,
                          int st)
{
    __shared__ float sO[Dd];
    const int b = blockIdx.y;
    const int n = blockIdx.x * 256 + threadIdx.x;
    for (int i = threadIdx.x; i < Dd; i += 256) sO[i] = sumO[b * Dd + i];
    __syncthreads();
    float acc = (float)Ss * bo[n];
    #pragma unroll 8
    for (int d = 0; d < Dd; d++)
        acc += sO[d] * Wo[(size_t)d * Dd + n];
    cat[b * (2 * Dd) + st * Dd + n] = acc;
}

// ---------------------------------------------------------------------------
// out[b,j] = tanh(cat[b,:] @ W_out[:,j] + b_out[j])
// ---------------------------------------------------------------------------
__global__ void final_kernel(const float* __restrict__ cat,
                             const float* __restrict__ Wout,
                             const float* __restrict__ bout,
                             float* __restrict__ out)
{
    __shared__ float sc[2 * Dd];
    const int b = blockIdx.x;
    const int j = threadIdx.x;      // 256 threads = KN outputs
    for (int i = threadIdx.x; i < 2 * Dd; i += 256) sc[i] = cat[b * (2 * Dd) + i];
    __syncthreads();
    float acc = bout[j];
    #pragma unroll 8
    for (int i = 0; i < 2 * Dd; i++)
        acc += sc[i] * Wout[(size_t)i * KN + j];
    out[b * KN + j] = tanhf(acc);
}

// ---------------------------------------------------------------------------
// Launch
// ---------------------------------------------------------------------------
extern "C" void kernel_launch(void* const* d_in, const int* in_sizes, int n_in,
                              void* d_out, int out_size)
{
    const int*   data0 = (const int*)  d_in[0];
    const float* know0 = (const float*)d_in[1];
    const int*   len0  = (const int*)  d_in[2];
    const int*   data1 = (const int*)  d_in[3];
    const float* know1 = (const float*)d_in[4];
    const int*   len1  = (const int*)  d_in[5];
    const float* emb   = (const float*)d_in[6];
    const float* Wt    = (const float*)d_in[7];
    const float* bt    = (const float*)d_in[8];
    const float* Wq[2] = {(const float*)d_in[9],  (const float*)d_in[17]};
    const float* bq[2] = {(const float*)d_in[10], (const float*)d_in[18]};
    const float* Wk[2] = {(const float*)d_in[11], (const float*)d_in[19]};
    const float* bk[2] = {(const float*)d_in[12], (const float*)d_in[20]};
    const float* Wv[2] = {(const float*)d_in[13], (const float*)d_in[21]};
    const float* bv[2] = {(const float*)d_in[14], (const float*)d_in[22]};
    const float* Wo[2] = {(const float*)d_in[15], (const float*)d_in[23]};
    const float* bo[2] = {(const float*)d_in[16], (const float*)d_in[24]};
    const float* Wout  = (const float*)d_in[25];
    const float* bout  = (const float*)d_in[26];
    float* out = (float*)d_out;

    const int*   datas[2] = {data0, data1};
    const float* knows[2] = {know0, know1};
    const int*   lens [2] = {len0, len1};

    float *pX, *pQ, *pK, *pV, *pS, *pIZ, *pC, *pSO, *pCat;
    cudaGetSymbolAddress((void**)&pX,  g_X);
    cudaGetSymbolAddress((void**)&pQ,  g_Q);
    cudaGetSymbolAddress((void**)&pK,  g_K);
    cudaGetSymbolAddress((void**)&pV,  g_V);
    cudaGetSymbolAddress((void**)&pS,  g_S);
    cudaGetSymbolAddress((void**)&pIZ, g_invZ);
    cudaGetSymbolAddress((void**)&pC,  g_c);
    cudaGetSymbolAddress((void**)&pSO, g_sumO);
    cudaGetSymbolAddress((void**)&pCat,g_cat);

    const dim3 gGemm(Mtot / 128, Dd / 64);     // 256 x 8
    const dim3 gScore(Ss / 128, Ss / 64, Bb);  // 16 x 32 x 16

    for (int st = 0; st < 2; st++) {
        // 1) embed:  X = (emb[data]*know) @ Wt + bt
        tf32_embed_gemm<<<gGemm, 256>>>(datas[st], knows[st], emb, Wt, bt, pX);
        // 2) Q (all rows), K,V (masked row-tiles skipped)
        tf32_gemm_bias<<<gGemm, 256>>>(pX, Wq[st], bq[st], pQ, Dd, nullptr);
        tf32_gemm_bias<<<gGemm, 256>>>(pX, Wk[st], bk[st], pK, Dd, lens[st]);
        tf32_gemm_bias<<<gGemm, 256>>>(pX, Wv[st], bv[st], pV, Dd, lens[st]);
        // 3) scores (masked k-tiles skipped)
        tf32_scores<<<gScore, 256>>>(pQ, pK, pS, lens[st]);
        // 4) softmax row stats (writes p in place) + column sums
        rowstats_kernel<<<Mtot, 256>>>(pS, pIZ, lens[st]);
        colsum_kernel<<<dim3(Ss / 256, Bb), 256>>>(pS, pIZ, pC, lens[st]);
        // 5) sumO = c @ V ; sa = sumO @ Wo + S*bo -> cat slot
        sumo_kernel<<<dim3(Dd / 128, Bb), 128>>>(pC, pV, pSO, lens[st]);
        sa_kernel<<<dim3(Dd / 256, Bb), 256>>>(pSO, Wo[st], bo[st], pCat, st);
    }
    // 6) out = tanh(cat @ Wout + bout)
    final_kernel<<<Bb, 256>>>(pCat, Wout, bout, out);
}

// round 6
// speedup vs baseline: 2.8704x; 1.1653x over previous
#include <cuda_runtime.h>
#include <math.h>
#include <stdint.h>

// Problem constants
#define Bb   16
#define Ss   2048
#define KN   256
#define Dd   512
#define Mtot (Bb * Ss)            // 32768
#define RSCALE 0.044194173824159216f  // 1/sqrt(512)

#define STR 136   // smem row stride (mod 32 = 8 -> conflict-free frag loads)

// ---------------------------------------------------------------------------
// Scratch
// ---------------------------------------------------------------------------
__device__ float g_X[Mtot * Dd];
__device__ float g_Q[Mtot * Dd];
__device__ float g_K[Mtot * Dd];
__device__ float g_V[Mtot * Dd];
__device__ float g_S[67108864];           // 256 MB scores / p values [B,S,S]
__device__ float g_invZ[Mtot];
__device__ float g_c[Mtot];
__device__ float g_sumO[Bb * Dd];
__device__ float g_cat[Bb * 2 * Dd];

// ---------------------------------------------------------------------------
// tf32 helpers
// ---------------------------------------------------------------------------
__device__ __forceinline__ uint32_t f2tf(float f) {
    uint32_t r;
    asm("cvt.rna.tf32.f32 %0, %1;" : "=r"(r) : "f"(f));
    return r;
}

__device__ __forceinline__ void mma8(float c[4], const uint32_t a[4], const uint32_t b[2]) {
    asm volatile(
        "mma.sync.aligned.m16n8k8.row.col.f32.tf32.tf32.f32 "
        "{%0,%1,%2,%3}, {%4,%5,%6,%7}, {%8,%9}, {%0,%1,%2,%3};"
        : "+f"(c[0]), "+f"(c[1]), "+f"(c[2]), "+f"(c[3])
        : "r"(a[0]), "r"(a[1]), "r"(a[2]), "r"(a[3]), "r"(b[0]), "r"(b[1]));
}

// Warp computes a 64(M) x 32(N) subtile of the 128x128 CTA tile.
// Warp grid: wm in {0,1} (M), wn in {0..3} (N).
__device__ __forceinline__ void compute_slab(const uint32_t As[16][STR],
                                             const uint32_t Bs[16][STR],
                                             float acc[4][4][4],
                                             int lane, int wm, int wn)
{
    const int grp = lane >> 2;   // 0..7
    const int qd  = lane & 3;    // 0..3
    const int mb0 = wm * 64;
    const int nb0 = wn * 32;
    #pragma unroll
    for (int ks = 0; ks < 2; ks++) {
        const int k0 = ks * 8;
        uint32_t a[4][4], b[4][2];
        #pragma unroll
        for (int tm = 0; tm < 4; tm++) {
            const int m = mb0 + tm * 16 + grp;
            a[tm][0] = As[k0 + qd][m];
            a[tm][1] = As[k0 + qd][m + 8];
            a[tm][2] = As[k0 + qd + 4][m];
            a[tm][3] = As[k0 + qd + 4][m + 8];
        }
        #pragma unroll
        for (int tn = 0; tn < 4; tn++) {
            const int n = nb0 + tn * 8 + grp;
            b[tn][0] = Bs[k0 + qd][n];
            b[tn][1] = Bs[k0 + qd + 4][n];
        }
        #pragma unroll
        for (int tm = 0; tm < 4; tm++)
            #pragma unroll
            for (int tn = 0; tn < 4; tn++)
                mma8(acc[tm][tn], a[tm], b[tn]);
    }
}

// ---------------------------------------------------------------------------
// tf32 GEMM: C[M,512] = A[M,Kd] @ W[Kd,512] + bias. Optional masked row-tiles.
// CTA 128x128, BK=16, 256 threads, double-buffered smem.
// ---------------------------------------------------------------------------
__global__ __launch_bounds__(256) void tf32_gemm_bias(const float* __restrict__ A,
                                                      const float* __restrict__ W,
                                                      const float* __restrict__ bias,
                                                      float* __restrict__ C,
                                                      int Kd,
                                                      const int* __restrict__ lens)
{
    __shared__ uint32_t As[2][16][STR];
    __shared__ uint32_t Bs[2][16][STR];
    const int tid  = threadIdx.x;
    const int lane = tid & 31;
    const int w    = tid >> 5;
    const int wm   = w >> 2, wn = w & 3;
    const int row0 = blockIdx.x * 128;
    const int col0 = blockIdx.y * 128;

    if (lens) {
        const int L = lens[row0 / Ss] + 1;
        if ((row0 % Ss) >= L) return;
    }

    const int ar  = tid >> 2;        // 0..63 (+64 second row)
    const int akq = (tid & 3) * 4;
    const int bk  = tid >> 4;        // 0..15
    const int bn  = (tid & 15) * 8;

    const float* pa0 = &A[(size_t)(row0 + ar) * Kd + akq];
    const float* pa1 = &A[(size_t)(row0 + ar + 64) * Kd + akq];
    const float* pw  = &W[(size_t)bk * Dd + col0 + bn];

    float4 ra0 = *(const float4*)pa0;
    float4 ra1 = *(const float4*)pa1;
    float4 rb0 = *(const float4*)pw;
    float4 rb1 = *(const float4*)(pw + 4);

    // stage 0
    As[0][akq + 0][ar] = f2tf(ra0.x); As[0][akq + 1][ar] = f2tf(ra0.y);
    As[0][akq + 2][ar] = f2tf(ra0.z); As[0][akq + 3][ar] = f2tf(ra0.w);
    As[0][akq + 0][ar + 64] = f2tf(ra1.x); As[0][akq + 1][ar + 64] = f2tf(ra1.y);
    As[0][akq + 2][ar + 64] = f2tf(ra1.z); As[0][akq + 3][ar + 64] = f2tf(ra1.w);
    {
        uint4 v0 = {f2tf(rb0.x), f2tf(rb0.y), f2tf(rb0.z), f2tf(rb0.w)};
        uint4 v1 = {f2tf(rb1.x), f2tf(rb1.y), f2tf(rb1.z), f2tf(rb1.w)};
        *(uint4*)&Bs[0][bk][bn]     = v0;
        *(uint4*)&Bs[0][bk][bn + 4] = v1;
    }
    __syncthreads();

    float acc[4][4][4] = {};
    int buf = 0;
    for (int kt = 0; kt < Kd; kt += 16) {
        const bool more = (kt + 16 < Kd);
        if (more) {
            ra0 = *(const float4*)(pa0 + kt + 16);
            ra1 = *(const float4*)(pa1 + kt + 16);
            rb0 = *(const float4*)(pw + (size_t)(kt + 16) * Dd);
            rb1 = *(const float4*)(pw + (size_t)(kt + 16) * Dd + 4);
        }
        compute_slab(As[buf], Bs[buf], acc, lane, wm, wn);
        if (more) {
            const int nb = buf ^ 1;
            As[nb][akq + 0][ar] = f2tf(ra0.x); As[nb][akq + 1][ar] = f2tf(ra0.y);
            As[nb][akq + 2][ar] = f2tf(ra0.z); As[nb][akq + 3][ar] = f2tf(ra0.w);
            As[nb][akq + 0][ar + 64] = f2tf(ra1.x); As[nb][akq + 1][ar + 64] = f2tf(ra1.y);
            As[nb][akq + 2][ar + 64] = f2tf(ra1.z); As[nb][akq + 3][ar + 64] = f2tf(ra1.w);
            uint4 v0 = {f2tf(rb0.x), f2tf(rb0.y), f2tf(rb0.z), f2tf(rb0.w)};
            uint4 v1 = {f2tf(rb1.x), f2tf(rb1.y), f2tf(rb1.z), f2tf(rb1.w)};
            *(uint4*)&Bs[nb][bk][bn]     = v0;
            *(uint4*)&Bs[nb][bk][bn + 4] = v1;
            __syncthreads();
            buf = nb;
        }
    }

    const int grp = lane >> 2, qd = lane & 3;
    #pragma unroll
    for (int tm = 0; tm < 4; tm++) {
        #pragma unroll
        for (int tn = 0; tn < 4; tn++) {
            const int r = row0 + wm * 64 + tm * 16 + grp;
            const int c = col0 + wn * 32 + tn * 8 + qd * 2;
            const float b0 = bias[c], b1 = bias[c + 1];
            C[(size_t)r * Dd + c]           = acc[tm][tn][0] + b0;
            C[(size_t)r * Dd + c + 1]       = acc[tm][tn][1] + b1;
            C[(size_t)(r + 8) * Dd + c]     = acc[tm][tn][2] + b0;
            C[(size_t)(r + 8) * Dd + c + 1] = acc[tm][tn][3] + b1;
        }
    }
}

// ---------------------------------------------------------------------------
// Embed GEMM (tf32): X = (emb[data]*know) @ W_t + b_t,  Kd = 256
// ---------------------------------------------------------------------------
__global__ __launch_bounds__(256) void tf32_embed_gemm(const int* __restrict__ data,
                                                       const float* __restrict__ know,
                                                       const float* __restrict__ emb,
                                                       const float* __restrict__ Wt,
                                                       const float* __restrict__ bt,
                                                       float* __restrict__ C)
{
    __shared__ uint32_t As[2][16][STR];
    __shared__ uint32_t Bs[2][16][STR];
    __shared__ int sIdx[128];
    const int tid  = threadIdx.x;
    const int lane = tid & 31;
    const int w    = tid >> 5;
    const int wm   = w >> 2, wn = w & 3;
    const int row0 = blockIdx.x * 128;
    const int col0 = blockIdx.y * 128;

    if (tid < 128) sIdx[tid] = data[row0 + tid];
    __syncthreads();

    const int ar  = tid >> 2;
    const int akq = (tid & 3) * 4;
    const int bk  = tid >> 4;
    const int bn  = (tid & 15) * 8;

    const float* pe0 = &emb[(size_t)sIdx[ar] * KN + akq];
    const float* pe1 = &emb[(size_t)sIdx[ar + 64] * KN + akq];
    const float* pk0 = &know[(size_t)(row0 + ar) * KN + akq];
    const float* pk1 = &know[(size_t)(row0 + ar + 64) * KN + akq];
    const float* pw  = &Wt[(size_t)bk * Dd + col0 + bn];

    float4 ea0 = *(const float4*)pe0;
    float4 ka0 = *(const float4*)pk0;
    float4 ea1 = *(const float4*)pe1;
    float4 ka1 = *(const float4*)pk1;
    float4 rb0 = *(const float4*)pw;
    float4 rb1 = *(const float4*)(pw + 4);

    As[0][akq + 0][ar] = f2tf(ea0.x * ka0.x); As[0][akq + 1][ar] = f2tf(ea0.y * ka0.y);
    As[0][akq + 2][ar] = f2tf(ea0.z * ka0.z); As[0][akq + 3][ar] = f2tf(ea0.w * ka0.w);
    As[0][akq + 0][ar + 64] = f2tf(ea1.x * ka1.x); As[0][akq + 1][ar + 64] = f2tf(ea1.y * ka1.y);
    As[0][akq + 2][ar + 64] = f2tf(ea1.z * ka1.z); As[0][akq + 3][ar + 64] = f2tf(ea1.w * ka1.w);
    {
        uint4 v0 = {f2tf(rb0.x), f2tf(rb0.y), f2tf(rb0.z), f2tf(rb0.w)};
        uint4 v1 = {f2tf(rb1.x), f2tf(rb1.y), f2tf(rb1.z), f2tf(rb1.w)};
        *(uint4*)&Bs[0][bk][bn]     = v0;
        *(uint4*)&Bs[0][bk][bn + 4] = v1;
    }
    __syncthreads();

    float acc[4][4][4] = {};
    int buf = 0;
    for (int kt = 0; kt < KN; kt += 16) {
        const bool more = (kt + 16 < KN);
        if (more) {
            ea0 = *(const float4*)(pe0 + kt + 16);
            ka0 = *(const float4*)(pk0 + kt + 16);
            ea1 = *(const float4*)(pe1 + kt + 16);
            ka1 = *(const float4*)(pk1 + kt + 16);
            rb0 = *(const float4*)(pw + (size_t)(kt + 16) * Dd);
            rb1 = *(const float4*)(pw + (size_t)(kt + 16) * Dd + 4);
        }
        compute_slab(As[buf], Bs[buf], acc, lane, wm, wn);
        if (more) {
            const int nb = buf ^ 1;
            As[nb][akq + 0][ar] = f2tf(ea0.x * ka0.x); As[nb][akq + 1][ar] = f2tf(ea0.y * ka0.y);
            As[nb][akq + 2][ar] = f2tf(ea0.z * ka0.z); As[nb][akq + 3][ar] = f2tf(ea0.w * ka0.w);
            As[nb][akq + 0][ar + 64] = f2tf(ea1.x * ka1.x); As[nb][akq + 1][ar + 64] = f2tf(ea1.y * ka1.y);
            As[nb][akq + 2][ar + 64] = f2tf(ea1.z * ka1.z); As[nb][akq + 3][ar + 64] = f2tf(ea1.w * ka1.w);
            uint4 v0 = {f2tf(rb0.x), f2tf(rb0.y), f2tf(rb0.z), f2tf(rb0.w)};
            uint4 v1 = {f2tf(rb1.x), f2tf(rb1.y), f2tf(rb1.z), f2tf(rb1.w)};
            *(uint4*)&Bs[nb][bk][bn]     = v0;
            *(uint4*)&Bs[nb][bk][bn + 4] = v1;
            __syncthreads();
            buf = nb;
        }
    }

    const int grp = lane >> 2, qd = lane & 3;
    #pragma unroll
    for (int tm = 0; tm < 4; tm++) {
        #pragma unroll
        for (int tn = 0; tn < 4; tn++) {
            const int r = row0 + wm * 64 + tm * 16 + grp;
            const int c = col0 + wn * 32 + tn * 8 + qd * 2;
            const float b0 = bt[c], b1 = bt[c + 1];
            C[(size_t)r * Dd + c]           = acc[tm][tn][0] + b0;
            C[(size_t)r * Dd + c + 1]       = acc[tm][tn][1] + b1;
            C[(size_t)(r + 8) * Dd + c]     = acc[tm][tn][2] + b0;
            C[(size_t)(r + 8) * Dd + c + 1] = acc[tm][tn][3] + b1;
        }
    }
}

// ---------------------------------------------------------------------------
// Scores (tf32, NT): S[b,q,k] = RSCALE * dot(Q[b,q,:], K[b,k,:]).
// CTA 128(q) x 128(k), BK=16 over D=512, double-buffered. Masked k-tiles skip.
// ---------------------------------------------------------------------------
__global__ __launch_bounds__(256) void tf32_scores(const float* __restrict__ Q,
                                                   const float* __restrict__ Km,
                                                   float* __restrict__ Sout,
                                                   const int* __restrict__ lens)
{
    const int b   = blockIdx.z;
    const int q0  = blockIdx.x * 128;
    const int k0c = blockIdx.y * 128;
    const int L   = lens[b] + 1;
    if (k0c >= L) return;

    __shared__ uint32_t As[2][16][STR];
    __shared__ uint32_t Bs[2][16][STR];
    const int tid  = threadIdx.x;
    const int lane = tid & 31;
    const int w    = tid >> 5;
    const int wm   = w >> 2, wn = w & 3;

    const float* Qb = Q  + (size_t)b * Ss * Dd;
    const float* Kb = Km + (size_t)b * Ss * Dd;

    const int ar  = tid >> 2;        // 0..63 (+64)
    const int akq = (tid & 3) * 4;

    const float* pa0 = &Qb[(size_t)(q0 + ar) * Dd + akq];
    const float* pa1 = &Qb[(size_t)(q0 + ar + 64) * Dd + akq];
    const float* pb0 = &Kb[(size_t)(k0c + ar) * Dd + akq];
    const float* pb1 = &Kb[(size_t)(k0c + ar + 64) * Dd + akq];

    float4 ra0 = *(const float4*)pa0;
    float4 ra1 = *(const float4*)pa1;
    float4 rb0 = *(const float4*)pb0;
    float4 rb1 = *(const float4*)pb1;

    As[0][akq + 0][ar] = f2tf(ra0.x); As[0][akq + 1][ar] = f2tf(ra0.y);
    As[0][akq + 2][ar] = f2tf(ra0.z); As[0][akq + 3][ar] = f2tf(ra0.w);
    As[0][akq + 0][ar + 64] = f2tf(ra1.x); As[0][akq + 1][ar + 64] = f2tf(ra1.y);
    As[0][akq + 2][ar + 64] = f2tf(ra1.z); As[0][akq + 3][ar + 64] = f2tf(ra1.w);
    Bs[0][akq + 0][ar] = f2tf(rb0.x); Bs[0][akq + 1][ar] = f2tf(rb0.y);
    Bs[0][akq + 2][ar] = f2tf(rb0.z); Bs[0][akq + 3][ar] = f2tf(rb0.w);
    Bs[0][akq + 0][ar + 64] = f2tf(rb1.x); Bs[0][akq + 1][ar + 64] = f2tf(rb1.y);
    Bs[0][akq + 2][ar + 64] = f2tf(rb1.z); Bs[0][akq + 3][ar + 64] = f2tf(rb1.w);
    __syncthreads();

    float acc[4][4][4] = {};
    int buf = 0;
    for (int kt = 0; kt < Dd; kt += 16) {
        const bool more = (kt + 16 < Dd);
        if (more) {
            ra0 = *(const float4*)(pa0 + kt + 16);
            ra1 = *(const float4*)(pa1 + kt + 16);
            rb0 = *(const float4*)(pb0 + kt + 16);
            rb1 = *(const float4*)(pb1 + kt + 16);
        }
        compute_slab(As[buf], Bs[buf], acc, lane, wm, wn);
        if (more) {
            const int nb = buf ^ 1;
            As[nb][akq + 0][ar] = f2tf(ra0.x); As[nb][akq + 1][ar] = f2tf(ra0.y);
            As[nb][akq + 2][ar] = f2tf(ra0.z); As[nb][akq + 3][ar] = f2tf(ra0.w);
            As[nb][akq + 0][ar + 64] = f2tf(ra1.x); As[nb][akq + 1][ar + 64] = f2tf(ra1.y);
            As[nb][akq + 2][ar + 64] = f2tf(ra1.z); As[nb][akq + 3][ar + 64] = f2tf(ra1.w);
            Bs[nb][akq + 0][ar] = f2tf(rb0.x); Bs[nb][akq + 1][ar] = f2tf(rb0.y);
            Bs[nb][akq + 2][ar] = f2tf(rb0.z); Bs[nb][akq + 3][ar] = f2tf(rb0.w);
            Bs[nb][akq + 0][ar + 64] = f2tf(rb1.x); Bs[nb][akq + 1][ar + 64] = f2tf(rb1.y);
            Bs[nb][akq + 2][ar + 64] = f2tf(rb1.z); Bs[nb][akq + 3][ar + 64] = f2tf(rb1.w);
            __syncthreads();
            buf = nb;
        }
    }

    float* Sb = Sout + (size_t)b * Ss * Ss;
    const int grp = lane >> 2, qd = lane & 3;
    #pragma unroll
    for (int tm = 0; tm < 4; tm++) {
        #pragma unroll
        for (int tn = 0; tn < 4; tn++) {
            const int q = q0 + wm * 64 + tm * 16 + grp;
            const int k = k0c + wn * 32 + tn * 8 + qd * 2;
            Sb[(size_t)q * Ss + k]           = acc[tm][tn][0] * RSCALE;
            Sb[(size_t)q * Ss + k + 1]       = acc[tm][tn][1] * RSCALE;
            Sb[(size_t)(q + 8) * Ss + k]     = acc[tm][tn][2] * RSCALE;
            Sb[(size_t)(q + 8) * Ss + k + 1] = acc[tm][tn][3] * RSCALE;
        }
    }
}

// ---------------------------------------------------------------------------
// Row stats: per (b,q) row: m = max, p = exp(s - m) in place, invZ = 1/sum(p)
// ---------------------------------------------------------------------------
__global__ void rowstats_kernel(float* __restrict__ Sm,
                                float* __restrict__ invZ,
                                const int* __restrict__ lens)
{
    __shared__ float red[256];
    const int r   = blockIdx.x;
    const int b   = r / Ss;
    const int L   = lens[b] + 1;
    const int tid = threadIdx.x;
    float* row = Sm + (size_t)r * Ss;

    float mx = -1e30f;
    for (int k = tid; k < L; k += 256) mx = fmaxf(mx, row[k]);
    red[tid] = mx;
    __syncthreads();
    for (int s = 128; s > 0; s >>= 1) {
        if (tid < s) red[tid] = fmaxf(red[tid], red[tid + s]);
        __syncthreads();
    }
    mx = red[0];
    __syncthreads();

    float z = 0.f;
    for (int k = tid; k < L; k += 256) {
        const float p = expf(row[k] - mx);
        row[k] = p;
        z += p;
    }
    red[tid] = z;
    __syncthreads();
    for (int s = 128; s > 0; s >>= 1) {
        if (tid < s) red[tid] += red[tid + s];
        __syncthreads();
    }
    if (tid == 0) invZ[r] = 1.0f / red[0];
}

// ---------------------------------------------------------------------------
// Column sums: c[b,k] = sum_q p[b,q,k] * invZ[b,q]
// ---------------------------------------------------------------------------
__global__ void colsum_kernel(const float* __restrict__ Sm,
                              const float* __restrict__ invZ,
                              float* __restrict__ c,
                              const int* __restrict__ lens)
{
    const int b = blockIdx.y;
    const int k = blockIdx.x * 256 + threadIdx.x;
    const int L = lens[b] + 1;
    if (k >= L) { c[b * Ss + k] = 0.0f; return; }

    const float* sp = Sm + (size_t)b * Ss * Ss + k;
    const float* iz = invZ + b * Ss;
    float acc = 0.f;
    #pragma unroll 1
    for (int q = 0; q < Ss; q += 8) {
        float p0 = sp[(size_t)(q + 0) * Ss];
        float p1 = sp[(size_t)(q + 1) * Ss];
        float p2 = sp[(size_t)(q + 2) * Ss];
        float p3 = sp[(size_t)(q + 3) * Ss];
        float p4 = sp[(size_t)(q + 4) * Ss];
        float p5 = sp[(size_t)(q + 5) * Ss];
        float p6 = sp[(size_t)(q + 6) * Ss];
        float p7 = sp[(size_t)(q + 7) * Ss];
        acc += p0 * iz[q + 0] + p1 * iz[q + 1] + p2 * iz[q + 2] + p3 * iz[q + 3]
             + p4 * iz[q + 4] + p5 * iz[q + 5] + p6 * iz[q + 6] + p7 * iz[q + 7];
    }
    c[b * Ss + k] = acc;
}

// ---------------------------------------------------------------------------
// sumO[b,d] = sum_{k<L} c[b,k] * V[b,k,d]
// ---------------------------------------------------------------------------
__global__ void sumo_kernel(const float* __restrict__ c,
                            const float* __restrict__ V,
                            float* __restrict__ sumO,
                            const int* __restrict__ lens)
{
    const int b = blockIdx.y;
    const int d = blockIdx.x * 128 + threadIdx.x;
    const int L = lens[b] + 1;
    const float* Vb = V + (size_t)b * Ss * Dd;
    const float* cb = c + b * Ss;
    float acc = 0.f;
    #pragma unroll 4
    for (int k = 0; k < L; k++)
        acc += cb[k] * Vb[(size_t)k * Dd + d];
    sumO[b * Dd + d] = acc;
}

// ---------------------------------------------------------------------------
// sa[b,n] = sumO[b,:] @ Wo[:,n] + S * bo[n]   -> g_cat[b, st*D + n]
// ---------------------------------------------------------------------------
__global__ void sa_kernel(const float* __restrict__ sumO,
                          const float* __restrict__ Wo,
                          const float* __restrict__ bo,
                          float* __restrict__ cat,
                          int st)
{
    __shared__ float sO[Dd];
    const int b = blockIdx.y;
    const int n = blockIdx.x * 256 + threadIdx.x;
    for (int i = threadIdx.x; i < Dd; i += 256) sO[i] = sumO[b * Dd + i];
    __syncthreads();
    float acc = (float)Ss * bo[n];
    #pragma unroll 8
    for (int d = 0; d < Dd; d++)
        acc += sO[d] * Wo[(size_t)d * Dd + n];
    cat[b * (2 * Dd) + st * Dd + n] = acc;
}

// ---------------------------------------------------------------------------
// out[b,j] = tanh(cat[b,:] @ W_out[:,j] + b_out[j])
// ---------------------------------------------------------------------------
__global__ void final_kernel(const float* __restrict__ cat,
                             const float* __restrict__ Wout,
                             const float* __restrict__ bout,
                             float* __restrict__ out)
{
    __shared__ float sc[2 * Dd];
    const int b = blockIdx.x;
    const int j = threadIdx.x;
    for (int i = threadIdx.x; i < 2 * Dd; i += 256) sc[i] = cat[b * (2 * Dd) + i];
    __syncthreads();
    float acc = bout[j];
    #pragma unroll 8
    for (int i = 0; i < 2 * Dd; i++)
        acc += sc[i] * Wout[(size_t)i * KN + j];
    out[b * KN + j] = tanhf(acc);
}

// ---------------------------------------------------------------------------
// Launch
// ---------------------------------------------------------------------------
extern "C" void kernel_launch(void* const* d_in, const int* in_sizes, int n_in,
                              void* d_out, int out_size)
{
    const int*   data0 = (const int*)  d_in[0];
    const float* know0 = (const float*)d_in[1];
    const int*   len0  = (const int*)  d_in[2];
    const int*   data1 = (const int*)  d_in[3];
    const float* know1 = (const float*)d_in[4];
    const int*   len1  = (const int*)  d_in[5];
    const float* emb   = (const float*)d_in[6];
    const float* Wt    = (const float*)d_in[7];
    const float* bt    = (const float*)d_in[8];
    const float* Wq[2] = {(const float*)d_in[9],  (const float*)d_in[17]};
    const float* bq[2] = {(const float*)d_in[10], (const float*)d_in[18]};
    const float* Wk[2] = {(const float*)d_in[11], (const float*)d_in[19]};
    const float* bk[2] = {(const float*)d_in[12], (const float*)d_in[20]};
    const float* Wv[2] = {(const float*)d_in[13], (const float*)d_in[21]};
    const float* bv[2] = {(const float*)d_in[14], (const float*)d_in[22]};
    const float* Wo[2] = {(const float*)d_in[15], (const float*)d_in[23]};
    const float* bo[2] = {(const float*)d_in[16], (const float*)d_in[24]};
    const float* Wout  = (const float*)d_in[25];
    const float* bout  = (const float*)d_in[26];
    float* out = (float*)d_out;

    const int*   datas[2] = {data0, data1};
    const float* knows[2] = {know0, know1};
    const int*   lens [2] = {len0, len1};

    float *pX, *pQ, *pK, *pV, *pS, *pIZ, *pC, *pSO, *pCat;
    cudaGetSymbolAddress((void**)&pX,  g_X);
    cudaGetSymbolAddress((void**)&pQ,  g_Q);
    cudaGetSymbolAddress((void**)&pK,  g_K);
    cudaGetSymbolAddress((void**)&pV,  g_V);
    cudaGetSymbolAddress((void**)&pS,  g_S);
    cudaGetSymbolAddress((void**)&pIZ, g_invZ);
    cudaGetSymbolAddress((void**)&pC,  g_c);
    cudaGetSymbolAddress((void**)&pSO, g_sumO);
    cudaGetSymbolAddress((void**)&pCat,g_cat);

    const dim3 gGemm(Mtot / 128, Dd / 128);     // 256 x 4
    const dim3 gScore(Ss / 128, Ss / 128, Bb);  // 16 x 16 x 16

    for (int st = 0; st < 2; st++) {
        tf32_embed_gemm<<<gGemm, 256>>>(datas[st], knows[st], emb, Wt, bt, pX);
        tf32_gemm_bias<<<gGemm, 256>>>(pX, Wq[st], bq[st], pQ, Dd, nullptr);
        tf32_gemm_bias<<<gGemm, 256>>>(pX, Wk[st], bk[st], pK, Dd, lens[st]);
        tf32_gemm_bias<<<gGemm, 256>>>(pX, Wv[st], bv[st], pV, Dd, lens[st]);
        tf32_scores<<<gScore, 256>>>(pQ, pK, pS, lens[st]);
        rowstats_kernel<<<Mtot, 256>>>(pS, pIZ, lens[st]);
        colsum_kernel<<<dim3(Ss / 256, Bb), 256>>>(pS, pIZ, pC, lens[st]);
        sumo_kernel<<<dim3(Dd / 128, Bb), 128>>>(pC, pV, pSO, lens[st]);
        sa_kernel<<<dim3(Dd / 256, Bb), 256>>>(pSO, Wo[st], bo[st], pCat, st);
    }
    final_kernel<<<Bb, 256>>>(pCat, Wout, bout, out);
}